// round 10
// baseline (speedup 1.0000x reference)
#include <cuda_runtime.h>

#define DM 24
#define RD 10
#define NSEQ 512
#define NBATCH 8
#define ROWS (NBATCH * NSEQ)          // 4096
#define APAD 12
#define NJSEG 16                      // j-segments per batch
#define JSEG 32                       // j rows per segment
#define CJP 36                        // padded col count for transposed j-data

typedef unsigned long long u64;

// Scratch (no runtime allocation allowed)
__device__ __align__(16) float g_A[ROWS * APAD];    // x_i @ W1[0:24] + b1
__device__ __align__(16) float g_Bv[ROWS * APAD];   // x_j @ W1[24:48]
__device__ __align__(16) float g_psum[NJSEG][ROWS * RD];
__device__ __align__(16) float g_pmax[NJSEG][ROWS * RD];

// ---------------- f32x2 helpers ----------------
__device__ __forceinline__ u64 pk(float lo, float hi) {
    u64 r; asm("mov.b64 %0, {%1, %2};" : "=l"(r) : "f"(lo), "f"(hi)); return r;
}
__device__ __forceinline__ void upk(float& lo, float& hi, u64 v) {
    asm("mov.b64 {%0, %1}, %2;" : "=f"(lo), "=f"(hi) : "l"(v));
}
__device__ __forceinline__ u64 f2fma(u64 a, u64 b, u64 c) {
    u64 d; asm("fma.rn.f32x2 %0, %1, %2, %3;" : "=l"(d) : "l"(a), "l"(b), "l"(c)); return d;
}
__device__ __forceinline__ u64 f2add(u64 a, u64 b) {
    u64 d; asm("add.rn.f32x2 %0, %1, %2;" : "=l"(d) : "l"(a), "l"(b)); return d;
}

// ---------------------------------------------------------------------------
// Kernel 1: per-row precompute of A_i = x_i@W1[0:24]+b1 and B_j = x_j@W1[24:48]
// ---------------------------------------------------------------------------
__global__ void precompute_kernel(const float* __restrict__ x,
                                  const float* __restrict__ W1,
                                  const float* __restrict__ b1) {
    int row = blockIdx.x * blockDim.x + threadIdx.x;
    if (row >= ROWS) return;
    float xv[DM];
#pragma unroll
    for (int d = 0; d < DM; d++) xv[d] = x[(size_t)row * DM + d];
    float A[RD], Bv[RD];
#pragma unroll
    for (int r = 0; r < RD; r++) { A[r] = b1[r]; Bv[r] = 0.f; }
#pragma unroll
    for (int d = 0; d < DM; d++) {
        float xd = xv[d];
#pragma unroll
        for (int r = 0; r < RD; r++) {
            A[r]  = fmaf(xd, W1[d * RD + r], A[r]);
            Bv[r] = fmaf(xd, W1[(DM + d) * RD + r], Bv[r]);
        }
    }
#pragma unroll
    for (int r = 0; r < RD; r++) {
        g_A[row * APAD + r]  = A[r];
        g_Bv[row * APAD + r] = Bv[r];
    }
    g_A[row * APAD + 10] = 0.f;  g_A[row * APAD + 11] = 0.f;
    g_Bv[row * APAD + 10] = 0.f; g_Bv[row * APAD + 11] = 0.f;
}

// ---------------------------------------------------------------------------
// Kernel 2: transposed pairwise. Each THREAD owns one i (ci/qi/Ai in regs).
// Block = 128 i's; j walks a 32-row segment; all smem reads are warp-uniform
// broadcasts. Partials written per (j-segment, i).
// ---------------------------------------------------------------------------
__global__ __launch_bounds__(128, 3)
void pair_kernel(const float* __restrict__ q,
                 const float* __restrict__ coord,
                 const float* __restrict__ W1,
                 const float* __restrict__ W2,
                 const float* __restrict__ b2) {
    __shared__ __align__(16) float s_cjT[DM][CJP];   // [d][j-local], 144B rows
    __shared__ __align__(16) float s_qjT[DM][CJP];
    __shared__ __align__(16) float s_bj[JSEG][12];   // B_j rows (48B stride)
    __shared__ __align__(16) float s_w1[26][12];     // [k][r]: k<24 |cdiff|, 24=qov, 25=dist
    __shared__ __align__(16) float s_w2[10][12];     // [rh][c]

    const int tid = threadIdx.x;
    const int bx  = blockIdx.x;
    const int ib  = bx >> 4;          // i-block 0..31
    const int js  = bx & 15;          // j-segment 0..15
    const int i   = ib * 128 + tid;   // this thread's row
    const int jb  = (ib >> 2) * NSEQ + js * JSEG;

    // --- weights to smem ---
    for (int idx = tid; idx < 26 * 12; idx += 128) {
        int d = idx / 12, r = idx % 12;
        float v = 0.f;
        if (r < RD) {
            int row = (d < 24) ? (48 + d) : (d == 24 ? 72 : 73);
            v = W1[row * RD + r];
        }
        s_w1[d][r] = v;
    }
    for (int idx = tid; idx < 10 * 12; idx += 128) {
        int rh = idx / 12, c = idx % 12;
        s_w2[rh][c] = (c < RD) ? W2[rh * RD + c] : 0.f;
    }
    // --- stage j-segment transposed: s_cjT[d][jl] ---
    for (int k = tid; k < JSEG * DM; k += 128) {
        int jl = k / DM, d = k % DM;
        s_cjT[d][jl] = coord[(size_t)(jb + jl) * DM + d];
        s_qjT[d][jl] = q[(size_t)(jb + jl) * DM + d];
    }
    // --- stage B_j (contiguous copy incl. pad) ---
    {
        const float4* gb = (const float4*)(g_Bv + (size_t)jb * APAD);
        float4* sb = (float4*)&s_bj[0][0];
        for (int k = tid; k < JSEG * 12 / 4; k += 128) sb[k] = gb[k];
    }

    // --- per-thread i-state in registers ---
    float ci[DM], qi[DM];
    {
        const float4* c4 = (const float4*)(coord + (size_t)i * DM);
        const float4* q4 = (const float4*)(q + (size_t)i * DM);
#pragma unroll
        for (int k = 0; k < 6; k++) {
            float4 t = c4[k]; ci[4*k]=t.x; ci[4*k+1]=t.y; ci[4*k+2]=t.z; ci[4*k+3]=t.w;
            float4 u = q4[k]; qi[4*k]=u.x; qi[4*k+1]=u.y; qi[4*k+2]=u.z; qi[4*k+3]=u.w;
        }
    }
    u64 aip[5];
#pragma unroll
    for (int t = 0; t < 5; t++) aip[t] = *(const u64*)(g_A + (size_t)i * APAD + 2 * t);
    u64 b2p[5];
#pragma unroll
    for (int t = 0; t < 5; t++) b2p[t] = pk(b2[2 * t], b2[2 * t + 1]);

    __syncthreads();

    float sacc[RD], macc[RD];
#pragma unroll
    for (int c = 0; c < RD; c++) { sacc[c] = 0.f; macc[c] = 0.f; }

#pragma unroll
    for (int jt = 0; jt < JSEG / 4; ++jt) {
        const int jl0 = jt * 4;
        // init: h = A_i + B_j
        u64 h2[4][5];
        float d2s[4], qds[4];
#pragma unroll
        for (int x = 0; x < 4; x++) {
            d2s[x] = 0.f; qds[x] = 0.f;
#pragma unroll
            for (int t = 0; t < 5; t++)
                h2[x][t] = f2add(aip[t], *(const u64*)&s_bj[jl0 + x][2 * t]);
        }
        // layer-1 |cdiff| block + d2/qdot
#pragma unroll
        for (int d = 0; d < DM; d++) {
            float4 cj4 = *(const float4*)&s_cjT[d][jl0];   // uniform broadcast
            float4 qj4 = *(const float4*)&s_qjT[d][jl0];   // uniform broadcast
            const float* cjp = &cj4.x;
            const float* qjp = &qj4.x;
            u64 av[4];
#pragma unroll
            for (int x = 0; x < 4; x++) {
                float df = ci[d] - cjp[x];
                d2s[x] = fmaf(df, df, d2s[x]);
                qds[x] = fmaf(qi[d], qjp[x], qds[x]);
                float ad = fabsf(df);
                av[x] = pk(ad, ad);
            }
#pragma unroll
            for (int t = 0; t < 5; t++) {
                u64 wv = *(const u64*)&s_w1[d][2 * t];
                h2[0][t] = f2fma(av[0], wv, h2[0][t]);
                h2[1][t] = f2fma(av[1], wv, h2[1][t]);
                h2[2][t] = f2fma(av[2], wv, h2[2][t]);
                h2[3][t] = f2fma(av[3], wv, h2[3][t]);
            }
        }
        // tail features: q_overlap, coord_dist
        u64 qp[4], dp[4];
#pragma unroll
        for (int x = 0; x < 4; x++) {
            float ds = sqrtf(d2s[x]);
            qp[x] = pk(qds[x], qds[x]);
            dp[x] = pk(ds, ds);
        }
#pragma unroll
        for (int t = 0; t < 5; t++) {
            u64 wq = *(const u64*)&s_w1[24][2 * t];
            u64 wd = *(const u64*)&s_w1[25][2 * t];
#pragma unroll
            for (int x = 0; x < 4; x++) {
                h2[x][t] = f2fma(qp[x], wq, h2[x][t]);
                h2[x][t] = f2fma(dp[x], wd, h2[x][t]);
            }
        }
        // layer 2 + accumulate, processed in x-pairs to cap live registers
#pragma unroll
        for (int xp = 0; xp < 2; xp++) {
            float ha[2][RD];
#pragma unroll
            for (int u = 0; u < 2; u++) {
                int x = 2 * xp + u;
#pragma unroll
                for (int t = 0; t < 5; t++) {
                    float lo, hi;
                    upk(lo, hi, h2[x][t]);
                    ha[u][2 * t]     = fmaxf(lo, 0.f);
                    ha[u][2 * t + 1] = fmaxf(hi, 0.f);
                }
            }
            u64 r2[2][5];
#pragma unroll
            for (int u = 0; u < 2; u++)
#pragma unroll
                for (int t = 0; t < 5; t++) r2[u][t] = b2p[t];
#pragma unroll
            for (int rh = 0; rh < RD; rh++) {
                u64 h0 = pk(ha[0][rh], ha[0][rh]);
                u64 h1 = pk(ha[1][rh], ha[1][rh]);
#pragma unroll
                for (int t = 0; t < 5; t++) {
                    u64 wv = *(const u64*)&s_w2[rh][2 * t];
                    r2[0][t] = f2fma(h0, wv, r2[0][t]);
                    r2[1][t] = f2fma(h1, wv, r2[1][t]);
                }
            }
#pragma unroll
            for (int u = 0; u < 2; u++) {
                int x = 2 * xp + u;
                const bool off = (jb + jl0 + x) != i;
                if (off) {
#pragma unroll
                    for (int t = 0; t < 5; t++) {
                        float r0, r1;
                        upk(r0, r1, r2[u][t]);
                        r0 = fmaxf(r0, 0.f); r1 = fmaxf(r1, 0.f);
                        sacc[2 * t]     += r0;  macc[2 * t]     = fmaxf(macc[2 * t], r0);
                        sacc[2 * t + 1] += r1;  macc[2 * t + 1] = fmaxf(macc[2 * t + 1], r1);
                    }
                }
            }
        }
    }

    // write partials (coalesced: thread i writes its own 10+10 floats)
#pragma unroll
    for (int c = 0; c < RD; c++) {
        g_psum[js][(size_t)i * RD + c] = sacc[c];
        g_pmax[js][(size_t)i * RD + c] = macc[c];
    }
}

// ---------------------------------------------------------------------------
// Kernel 3: reduce 16 j-segment partials -> final mean / max
// ---------------------------------------------------------------------------
__global__ void reduce_kernel(float* __restrict__ out) {
    int gid = blockIdx.x * blockDim.x + threadIdx.x;
    if (gid >= ROWS * RD) return;
    float s = 0.f, m = 0.f;
#pragma unroll
    for (int js = 0; js < NJSEG; js++) {
        s += g_psum[js][gid];
        m = fmaxf(m, g_pmax[js][gid]);
    }
    out[gid] = s * (1.0f / (float)(NSEQ - 1));
    out[ROWS * RD + gid] = m;
}

// ---------------------------------------------------------------------------
extern "C" void kernel_launch(void* const* d_in, const int* in_sizes, int n_in,
                              void* d_out, int out_size) {
    const float* x     = (const float*)d_in[0];
    const float* q     = (const float*)d_in[1];
    const float* coord = (const float*)d_in[2];
    const float* W1    = (const float*)d_in[3];
    const float* b1    = (const float*)d_in[4];
    const float* W2    = (const float*)d_in[5];
    const float* b2    = (const float*)d_in[6];
    float* out = (float*)d_out;

    precompute_kernel<<<(ROWS + 127) / 128, 128>>>(x, W1, b1);
    pair_kernel<<<32 * NJSEG, 128>>>(q, coord, W1, W2, b2);
    reduce_kernel<<<(ROWS * RD + 255) / 256, 256>>>(out);
}

// round 11
// speedup vs baseline: 1.8594x; 1.8594x over previous
#include <cuda_runtime.h>

#define DM 24
#define RD 10
#define NSEQ 512
#define NBATCH 8
#define ROWS (NBATCH * NSEQ)          // 4096
#define APAD 12
#define CQS 52                        // padded row stride for staged cj/qj
#define JCH 128                       // j-chunk rows per superiter
#define NWARP 8                       // warps (=i's) per block
#define BLKT (NWARP * 32)             // 256 threads

typedef unsigned long long u64;

// Scratch (no runtime allocation allowed)
__device__ __align__(16) float g_A[ROWS * APAD];    // x_i @ W1[0:24] + b1
__device__ __align__(16) float g_Bv[ROWS * APAD];   // x_j @ W1[24:48]

// ---------------- f32x2 helpers ----------------
__device__ __forceinline__ u64 pk(float lo, float hi) {
    u64 r; asm("mov.b64 %0, {%1, %2};" : "=l"(r) : "f"(lo), "f"(hi)); return r;
}
__device__ __forceinline__ void upk(float& lo, float& hi, u64 v) {
    asm("mov.b64 {%0, %1}, %2;" : "=f"(lo), "=f"(hi) : "l"(v));
}
__device__ __forceinline__ u64 f2fma(u64 a, u64 b, u64 c) {
    u64 d; asm("fma.rn.f32x2 %0, %1, %2, %3;" : "=l"(d) : "l"(a), "l"(b), "l"(c)); return d;
}
__device__ __forceinline__ u64 f2add(u64 a, u64 b) {
    u64 d; asm("add.rn.f32x2 %0, %1, %2;" : "=l"(d) : "l"(a), "l"(b)); return d;
}

// ---------------------------------------------------------------------------
// Kernel 1: per-row precompute (vectorized x loads)
// ---------------------------------------------------------------------------
__global__ void precompute_kernel(const float* __restrict__ x,
                                  const float* __restrict__ W1,
                                  const float* __restrict__ b1) {
    int row = blockIdx.x * blockDim.x + threadIdx.x;
    if (row >= ROWS) return;
    float xv[DM];
    {
        const float4* x4 = (const float4*)(x + (size_t)row * DM);
#pragma unroll
        for (int k = 0; k < 6; k++) {
            float4 t = x4[k];
            xv[4*k] = t.x; xv[4*k+1] = t.y; xv[4*k+2] = t.z; xv[4*k+3] = t.w;
        }
    }
    float A[RD], Bv[RD];
#pragma unroll
    for (int r = 0; r < RD; r++) { A[r] = b1[r]; Bv[r] = 0.f; }
#pragma unroll
    for (int d = 0; d < DM; d++) {
        float xd = xv[d];
#pragma unroll
        for (int r = 0; r < RD; r++) {
            A[r]  = fmaf(xd, W1[d * RD + r], A[r]);
            Bv[r] = fmaf(xd, W1[(DM + d) * RD + r], Bv[r]);
        }
    }
#pragma unroll
    for (int r = 0; r < RD; r++) {
        g_A[row * APAD + r]  = A[r];
        g_Bv[row * APAD + r] = Bv[r];
    }
    g_A[row * APAD + 10] = 0.f;  g_A[row * APAD + 11] = 0.f;
    g_Bv[row * APAD + 10] = 0.f; g_Bv[row * APAD + 11] = 0.f;
}

// ---------------------------------------------------------------------------
// Kernel 2: pairwise. 8 warps per block, 1 warp per i; per superiter the BLOCK
// stages a 128-row j-chunk shared by all 8 warps; each lane handles 4 j's.
// ---------------------------------------------------------------------------
__global__ __launch_bounds__(BLKT, 2)
void pair_kernel(const float* __restrict__ q,
                 const float* __restrict__ coord,
                 const float* __restrict__ W1,
                 const float* __restrict__ W2,
                 const float* __restrict__ b2,
                 float* __restrict__ out) {
    __shared__ __align__(16) float s_cq[JCH][CQS];   // [r][0:24)=coord_j, [24:48)=q_j (208B stride)
    __shared__ __align__(16) float s_bj[JCH][14];    // B_j rows (56B stride; float2/u64 access only)
    __shared__ __align__(16) float s_w1[26][12];     // [k][r]: k<24 |cdiff| rows, 24=qov, 25=dist
    __shared__ __align__(16) float s_w2[10][12];     // [rh][c] = W2[rh][c]
    __shared__ __align__(16) float s_ciq[NWARP][CQS];// per-warp: ci (0..23), qi (24..47)
    __shared__ __align__(16) float s_ai[NWARP][12];  // per-warp: A_i

    const int tid = threadIdx.x;
    const int w = tid >> 5, lane = tid & 31;
    const int i = blockIdx.x * NWARP + w;
    const int jbase = i & ~(NSEQ - 1);

    // --- one-time fills ---
    for (int idx = tid; idx < 26 * 12; idx += BLKT) {
        int d = idx / 12, r = idx % 12;
        float v = 0.f;
        if (r < RD) {
            int row = (d < 24) ? (48 + d) : (d == 24 ? 72 : 73);
            v = W1[row * RD + r];
        }
        s_w1[d][r] = v;
    }
    for (int idx = tid; idx < 10 * 12; idx += BLKT) {
        int rh = idx / 12, c = idx % 12;
        s_w2[rh][c] = (c < RD) ? W2[rh * RD + c] : 0.f;
    }
    if (lane < DM) {
        s_ciq[w][lane]      = coord[(size_t)i * DM + lane];
        s_ciq[w][24 + lane] = q[(size_t)i * DM + lane];
    }
    if (lane < 12) s_ai[w][lane] = g_A[i * APAD + lane];

    u64 b2p[5];
#pragma unroll
    for (int t = 0; t < 5; t++) b2p[t] = pk(b2[2 * t], b2[2 * t + 1]);

    float sacc[RD], macc[RD];
#pragma unroll
    for (int c = 0; c < RD; c++) { sacc[c] = 0.f; macc[c] = 0.f; }

    for (int it = 0; it < NSEQ / JCH; ++it) {
        const int jb = jbase + it * JCH;
        __syncthreads();
        // --- stage 128 j-rows, block-wide (coalesced) ---
        {
            const float4* gc = (const float4*)(coord + (size_t)jb * DM);
            const float4* gq = (const float4*)(q + (size_t)jb * DM);
#pragma unroll
            for (int k = tid; k < JCH * 6; k += BLKT) {      // 128*24/4 = 768
                int r = k / 6, c = (k % 6) * 4;
                *(float4*)&s_cq[r][c]      = gc[k];
                *(float4*)&s_cq[r][24 + c] = gq[k];
            }
            const float2* gb = (const float2*)(g_Bv + (size_t)jb * APAD);
#pragma unroll
            for (int k = tid; k < JCH * 6; k += BLKT) {      // 128*12/2 = 768
                int r = k / 6, c = (k % 6) * 2;
                *(float2*)&s_bj[r][c] = gb[k];
            }
        }
        __syncthreads();

        // --- per-lane: 4 pairs (i, jb + lane + 32x) ---
        u64 h2[4][5];
        float d2s[4], qds[4];
#pragma unroll
        for (int x = 0; x < 4; x++) {
            d2s[x] = 0.f; qds[x] = 0.f;
#pragma unroll
            for (int t = 0; t < 5; t++) {
                u64 ai = *(const u64*)&s_ai[w][2 * t];
                h2[x][t] = f2add(ai, *(const u64*)&s_bj[32 * x + lane][2 * t]);
            }
        }

#pragma unroll
        for (int kk = 0; kk < 6; ++kk) {
            float4 ci4 = *(const float4*)&s_ciq[w][4 * kk];
            float4 qi4 = *(const float4*)&s_ciq[w][24 + 4 * kk];
            float4 cj[4], qj[4];
#pragma unroll
            for (int x = 0; x < 4; x++) {
                cj[x] = *(const float4*)&s_cq[32 * x + lane][4 * kk];
                qj[x] = *(const float4*)&s_cq[32 * x + lane][24 + 4 * kk];
            }
            const float* cip = &ci4.x; const float* qip = &qi4.x;
#pragma unroll
            for (int e = 0; e < 4; e++) {
                const int d = 4 * kk + e;
                u64 av[4];
#pragma unroll
                for (int x = 0; x < 4; x++) {
                    const float* cjp = &cj[x].x;
                    const float* qjp = &qj[x].x;
                    float df = cip[e] - cjp[e];
                    d2s[x] = fmaf(df, df, d2s[x]);
                    qds[x] = fmaf(qip[e], qjp[e], qds[x]);
                    float ad = fabsf(df);
                    av[x] = pk(ad, ad);
                }
#pragma unroll
                for (int t = 0; t < 5; t++) {
                    u64 wv = *(const u64*)&s_w1[d][2 * t];
                    h2[0][t] = f2fma(av[0], wv, h2[0][t]);
                    h2[1][t] = f2fma(av[1], wv, h2[1][t]);
                    h2[2][t] = f2fma(av[2], wv, h2[2][t]);
                    h2[3][t] = f2fma(av[3], wv, h2[3][t]);
                }
            }
        }
        // tail features: q_overlap, coord_dist
        u64 qp[4], dp[4];
#pragma unroll
        for (int x = 0; x < 4; x++) {
            float ds = sqrtf(d2s[x]);
            qp[x] = pk(qds[x], qds[x]);
            dp[x] = pk(ds, ds);
        }
#pragma unroll
        for (int t = 0; t < 5; t++) {
            u64 wq = *(const u64*)&s_w1[24][2 * t];
            u64 wd = *(const u64*)&s_w1[25][2 * t];
#pragma unroll
            for (int x = 0; x < 4; x++) {
                h2[x][t] = f2fma(qp[x], wq, h2[x][t]);
                h2[x][t] = f2fma(dp[x], wd, h2[x][t]);
            }
        }
        // relu -> hidden scalars
        float ha[4][RD];
#pragma unroll
        for (int x = 0; x < 4; x++) {
#pragma unroll
            for (int t = 0; t < 5; t++) {
                float lo, hi;
                upk(lo, hi, h2[x][t]);
                ha[x][2 * t]     = fmaxf(lo, 0.f);
                ha[x][2 * t + 1] = fmaxf(hi, 0.f);
            }
        }

        // layer 2: each weight LDS feeds 4 pairs
        u64 r2[4][5];
#pragma unroll
        for (int x = 0; x < 4; x++)
#pragma unroll
            for (int t = 0; t < 5; t++) r2[x][t] = b2p[t];
#pragma unroll
        for (int rh = 0; rh < RD; rh++) {
            u64 hh[4];
#pragma unroll
            for (int x = 0; x < 4; x++) hh[x] = pk(ha[x][rh], ha[x][rh]);
#pragma unroll
            for (int t = 0; t < 5; t++) {
                u64 wv = *(const u64*)&s_w2[rh][2 * t];
                r2[0][t] = f2fma(hh[0], wv, r2[0][t]);
                r2[1][t] = f2fma(hh[1], wv, r2[1][t]);
                r2[2][t] = f2fma(hh[2], wv, r2[2][t]);
                r2[3][t] = f2fma(hh[3], wv, r2[3][t]);
            }
        }
        // relu + masked accumulate
#pragma unroll
        for (int x = 0; x < 4; x++) {
            const bool off = (jb + 32 * x + lane) != i;
            if (off) {
#pragma unroll
                for (int t = 0; t < 5; t++) {
                    float r0, r1;
                    upk(r0, r1, r2[x][t]);
                    r0 = fmaxf(r0, 0.f); r1 = fmaxf(r1, 0.f);
                    sacc[2 * t]     += r0;  macc[2 * t]     = fmaxf(macc[2 * t], r0);
                    sacc[2 * t + 1] += r1;  macc[2 * t + 1] = fmaxf(macc[2 * t + 1], r1);
                }
            }
        }
    }

    // warp reduction across j-lanes (deterministic tree)
#pragma unroll
    for (int c = 0; c < RD; c++) {
#pragma unroll
        for (int o = 16; o > 0; o >>= 1) {
            sacc[c] += __shfl_xor_sync(0xffffffffu, sacc[c], o);
            macc[c] = fmaxf(macc[c], __shfl_xor_sync(0xffffffffu, macc[c], o));
        }
    }
    if (lane == 0) {
        const float inv = 1.0f / (float)(NSEQ - 1);
#pragma unroll
        for (int c = 0; c < RD; c++) {
            out[(size_t)i * RD + c] = sacc[c] * inv;
            out[(size_t)ROWS * RD + (size_t)i * RD + c] = macc[c];
        }
    }
}

// ---------------------------------------------------------------------------
extern "C" void kernel_launch(void* const* d_in, const int* in_sizes, int n_in,
                              void* d_out, int out_size) {
    const float* x     = (const float*)d_in[0];
    const float* q     = (const float*)d_in[1];
    const float* coord = (const float*)d_in[2];
    const float* W1    = (const float*)d_in[3];
    const float* b1    = (const float*)d_in[4];
    const float* W2    = (const float*)d_in[5];
    const float* b2    = (const float*)d_in[6];
    float* out = (float*)d_out;

    precompute_kernel<<<(ROWS + 127) / 128, 128>>>(x, W1, b1);
    pair_kernel<<<ROWS / NWARP, BLKT>>>(q, coord, W1, W2, b2, out);
}